// round 5
// baseline (speedup 1.0000x reference)
#include <cuda_runtime.h>
#include <math.h>

// ---------------------------------------------------------------------------
// GRAPEIso: conv3x3(3->1024) + pixel_shuffle(4) + pixel_unshuffle(2) + head
// algebraically folded into a 96-output 3x3 conv, then Gaussian splatting
// with exclusive shared-memory image tiles (no global atomics).
// Fixed shapes: B=4, inp 3x128x128, scale=2, grid 256x256 gaussians/batch,
// image 4x3x256x256 fp32 output.
// ---------------------------------------------------------------------------

#define BATCH   4
#define INH     128
#define INW     128
#define GH      256
#define GW      256
#define IMH     256
#define IMW     256
#define NGAUSS  (GH * GW)

// Raster tiling: 16x16 image tile per CTA -> 1024 CTAs. 4x4 footprint,
// 22x22 gather halo.
#define TW      16
#define TH      16
#define RSX     22
#define RSY     22

typedef unsigned long long ull;

#define FMA_F32X2(acc, a, b) \
    asm("fma.rn.f32x2 %0, %1, %2, %0;" : "+l"(acc) : "l"(a), "l"(b))
#define PACK_F32X2(out, lo, hi) \
    asm("mov.b64 %0, {%1, %2};" : "=l"(out) : "f"(lo), "f"(hi))
#define UNPACK_F32X2(lo, hi, in) \
    asm("mov.b64 {%0, %1}, %2;" : "=f"(lo), "=f"(hi) : "l"(in))

__device__ __forceinline__ float tanh_approx(float x) {
    float r;
    asm("tanh.approx.f32 %0, %1;" : "=f"(r) : "f"(x));
    return r;
}

// Scratch (allocation-free contract: __device__ globals)
__device__ float  g_weff[4 * 27 * 24];          // [uv][t][o], o contiguous
__device__ float  g_beff[4 * 24];               // [uv][o]
__device__ float2 g_center[BATCH * NGAUSS];     // (cx, cy)
__device__ float4 g_color [BATCH * NGAUSS];     // (r, g, b, pad)

// ---------------------------------------------------------------------------
// Kernel 0: weight fold. One CTA per (uv, o): 96 CTAs x 256 threads.
// Thread = channel ch: w_head load coalesced; each thread streams its own
// 27-float w_enc row (rows L2-shared by the 24 o-CTAs of the same uv).
// 28 accumulators (27 weights + bias term), shfl + smem tree reduce.
// ---------------------------------------------------------------------------
__global__ void __launch_bounds__(256) fold_kernel(
    const float* __restrict__ w_enc,   // (1024, 3, 3, 3) -> [C*27 + t]
    const float* __restrict__ b_enc,   // (1024,)
    const float* __restrict__ w_head,  // (24, 256)
    const float* __restrict__ b_head)  // (24,)
{
    __shared__ float red[8][28];

    int uv = blockIdx.x / 24;
    int o  = blockIdx.x - uv * 24;
    int u = uv >> 1, v = uv & 1;

    int ch   = threadIdx.x;
    int warp = ch >> 5;
    int lane = ch & 31;

    int c = ch >> 2, a = (ch >> 1) & 1, e = ch & 1;
    int C = c * 16 + (2 * u + a) * 4 + (2 * v + e);

    float wh = __ldg(w_head + o * 256 + ch);
    const float* we = w_enc + C * 27;

    float acc[28];
    #pragma unroll
    for (int t = 0; t < 27; t++) acc[t] = wh * __ldg(we + t);
    acc[27] = wh * __ldg(b_enc + C);

    #pragma unroll
    for (int t = 0; t < 28; t++) {
        #pragma unroll
        for (int s = 16; s; s >>= 1)
            acc[t] += __shfl_xor_sync(~0u, acc[t], s);
    }
    if (lane == 0) {
        #pragma unroll
        for (int t = 0; t < 28; t++) red[warp][t] = acc[t];
    }
    __syncthreads();

    if (threadIdx.x < 28) {
        int t = threadIdx.x;
        float s = 0.f;
        #pragma unroll
        for (int w = 0; w < 8; w++) s += red[w][t];
        if (t < 27) g_weff[uv * 648 + t * 24 + o] = s;
        else        g_beff[uv * 24 + o] = s + b_head[o];
    }
}

// ---------------------------------------------------------------------------
// Kernel 1: predict. 512 CTAs x 128 threads; CTA = 16x8 input tile of one
// batch. Input tile (+1 halo) staged in smem with coalesced loads; folded
// weights in smem (LDS.128 warp-broadcast); packed f32x2 FFMA main loop
// (patch kept ONLY in packed form -> no r3 register blowup); tanh.approx.
// ---------------------------------------------------------------------------
__global__ void __launch_bounds__(128) predict_kernel(const float* __restrict__ inp)
{
    __shared__ __align__(16) float sW[4 * 648];      // [uv][t][o]
    __shared__ float sB[96];
    __shared__ float sIn[3 * 10 * 18];               // [c][y][x], halo=1

    int tile = blockIdx.x & 127;
    int b    = blockIdx.x >> 7;
    int tx0  = (tile & 7) * 16;        // 8 tiles across
    int ty0  = (tile >> 3) * 8;        // 16 tiles down

    for (int i = threadIdx.x; i < 4 * 648; i += 128) sW[i] = g_weff[i];
    if (threadIdx.x < 96) sB[threadIdx.x] = g_beff[threadIdx.x];

    const float* ib = inp + (size_t)b * 3 * INH * INW;
    for (int idx = threadIdx.x; idx < 540; idx += 128) {
        int c = idx / 180, rem = idx - c * 180;
        int y = rem / 18,  x = rem - y * 18;
        int gy = ty0 - 1 + y, gx = tx0 - 1 + x;
        float vv = 0.f;
        if ((unsigned)gy < INH && (unsigned)gx < INW)
            vv = ib[c * INH * INW + gy * INW + gx];
        sIn[idx] = vv;
    }
    __syncthreads();

    int tx = threadIdx.x & 15;
    int ty = threadIdx.x >> 4;
    int i  = ty0 + ty;
    int j  = tx0 + tx;

    // patch, packed (x,x) only
    ull patch2[27];
    #pragma unroll
    for (int ic = 0; ic < 3; ic++)
        #pragma unroll
        for (int ky = 0; ky < 3; ky++)
            #pragma unroll
            for (int kx = 0; kx < 3; kx++) {
                float vv = sIn[ic * 180 + (ty + ky) * 18 + (tx + kx)];
                PACK_F32X2(patch2[ic * 9 + ky * 3 + kx], vv, vv);
            }

    #pragma unroll
    for (int uv = 0; uv < 4; uv++) {
        ull acc2[12];
        #pragma unroll
        for (int q = 0; q < 12; q++)
            PACK_F32X2(acc2[q], sB[uv * 24 + 2 * q], sB[uv * 24 + 2 * q + 1]);

        const ulonglong2* wrow = (const ulonglong2*)(sW + uv * 648);
        #pragma unroll
        for (int t = 0; t < 27; t++) {
            ull xv2 = patch2[t];
            #pragma unroll
            for (int q = 0; q < 6; q++) {
                ulonglong2 w2 = wrow[t * 6 + q];     // 4 weights = 2 f32x2
                FMA_F32X2(acc2[2 * q],     w2.x, xv2);
                FMA_F32X2(acc2[2 * q + 1], w2.y, xv2);
            }
        }

        float acc[24];
        #pragma unroll
        for (int q = 0; q < 12; q++)
            UNPACK_F32X2(acc[2 * q], acc[2 * q + 1], acc2[q]);

        // acc[k*6+d]: d=0..2 rgb, 3..4 off, 5 logit ; K=4
        float lg0 = acc[5], lg1 = acc[11], lg2 = acc[17], lg3 = acc[23];
        float m = fmaxf(fmaxf(lg0, lg1), fmaxf(lg2, lg3));
        float w0 = __expf(lg0 - m), w1 = __expf(lg1 - m);
        float w2 = __expf(lg2 - m), w3 = __expf(lg3 - m);
        float inv = 1.f / (w0 + w1 + w2 + w3);

        float r = 0.f, g = 0.f, bl = 0.f, ox = 0.f, oy = 0.f;
        #pragma unroll
        for (int k = 0; k < 4; k++) {
            float wk = ((k == 0) ? w0 : (k == 1) ? w1 : (k == 2) ? w2 : w3) * inv;
            r  = fmaf(acc[k * 6 + 0], wk, r);
            g  = fmaf(acc[k * 6 + 1], wk, g);
            bl = fmaf(acc[k * 6 + 2], wk, bl);
            ox = fmaf(tanh_approx(acc[k * 6 + 3]), wk, ox);
            oy = fmaf(tanh_approx(acc[k * 6 + 4]), wk, oy);
        }

        int u = uv >> 1, v = uv & 1;
        int gy = 2 * i + u, gx = 2 * j + v;
        float cx = (float)gx + 2.f * ox - 1.f;
        float cy = (float)gy + 2.f * oy - 1.f;

        int gidx = b * NGAUSS + gy * GW + gx;
        g_center[gidx] = make_float2(cx, cy);
        g_color[gidx]  = make_float4(r, g, bl, 0.f);
    }
}

// ---------------------------------------------------------------------------
// Kernel 2: rasterize (unchanged from r4 - single-variable discipline).
// One CTA per 16x16 tile per batch (1024 CTAs). Effective footprint is 4x4
// (alpha cutoff kills |d|>=2). Gather halo 22x22; stride-5 lane permutation
// keeps smem atomics conflict-free.
// ---------------------------------------------------------------------------
__global__ void __launch_bounds__(256) raster_kernel(float* __restrict__ out)
{
    __shared__ float acc[3 * TH * TW];  // [ch][ty][tx]

    int tx0 = (blockIdx.x & 15) * TW;
    int ty0 = (blockIdx.x >> 4) * TH;
    int b   = blockIdx.y;

    for (int p = threadIdx.x; p < 3 * TH * TW; p += 256) acc[p] = 0.f;
    __syncthreads();

    const float2* ctr = g_center + b * NGAUSS;
    const float4* col = g_color  + b * NGAUSS;

    for (int idx = threadIdx.x; idx < RSX * RSY; idx += 256) {
        int ry = idx / RSX;
        int j  = idx - ry * RSX;
        int rx = (j * 5) % RSX;
        int gy = ty0 - 2 + ry;
        int gx = tx0 - 2 + rx;
        if ((unsigned)gy >= GH || (unsigned)gx >= GW) continue;

        int gi = gy * GW + gx;
        float2 c = ctr[gi];

        float ixf = floorf(c.x);
        float iyf = floorf(c.y);

        int txl = (int)ixf - 1 - tx0;
        int tyl = (int)iyf - 1 - ty0;
        if (txl >= TW || txl <= -4 || tyl >= TH || tyl <= -4) continue;

        float4 rgbv = col[gi];

        float ex[4], ey[4];
        #pragma unroll
        for (int o = 0; o < 4; o++) {
            float dx = ixf + (float)(o - 1) - c.x;
            float dy = iyf + (float)(o - 1) - c.y;
            ex[o] = __expf(-2.f * dx * dx);
            ey[o] = __expf(-2.f * dy * dy);
        }

        #pragma unroll
        for (int oy = 0; oy < 4; oy++) {
            int ty = tyl + oy;
            if ((unsigned)ty >= TH) continue;
            float eyv = ey[oy];
            #pragma unroll
            for (int ox = 0; ox < 4; ox++) {
                int tx = txl + ox;
                if ((unsigned)tx >= TW) continue;
                float a = fminf(eyv * ex[ox], 0.999f);
                if (a > (1.0f / 255.0f)) {
                    int p = ty * TW + tx;
                    atomicAdd(&acc[p],               a * rgbv.x);
                    atomicAdd(&acc[TH * TW + p],     a * rgbv.y);
                    atomicAdd(&acc[2 * TH * TW + p], a * rgbv.z);
                }
            }
        }
    }
    __syncthreads();

    float* ob = out + (size_t)b * 3 * IMH * IMW;
    for (int p = threadIdx.x; p < TH * TW; p += 256) {
        int ty = p >> 4;
        int tx = p & 15;
        int o  = (ty0 + ty) * IMW + (tx0 + tx);
        #pragma unroll
        for (int ch = 0; ch < 3; ch++) {
            float vv = acc[ch * TH * TW + p];
            ob[ch * IMH * IMW + o] = fminf(fmaxf(vv, 0.f), 1.f);
        }
    }
}

// ---------------------------------------------------------------------------
// Launch: fold -> predict -> raster, all graph-capturable, no allocs/syncs.
// Inputs (metadata order): inp, w_enc, b_enc, w_head, b_head, scale(unused)
// ---------------------------------------------------------------------------
extern "C" void kernel_launch(void* const* d_in, const int* in_sizes, int n_in,
                              void* d_out, int out_size)
{
    const float* inp    = (const float*)d_in[0];
    const float* w_enc  = (const float*)d_in[1];
    const float* b_enc  = (const float*)d_in[2];
    const float* w_head = (const float*)d_in[3];
    const float* b_head = (const float*)d_in[4];
    float* out = (float*)d_out;

    fold_kernel<<<96, 256>>>(w_enc, b_enc, w_head, b_head);
    predict_kernel<<<512, 128>>>(inp);

    dim3 g(256, BATCH);
    raster_kernel<<<g, 256>>>(out);
}